// round 8
// baseline (speedup 1.0000x reference)
#include <cuda_runtime.h>

#define NBANDS 31
#define NB     16
#define NT     1000
#define NF     257
#define NO     128
#define MAXC   34
#define KTOT   536      // sum of roundup4(2*bw)
#define TT     4        // time tile per block
#define NCH    8        // stats chunks per (b,band)
#define OUTW   (NO * NBANDS)   // 3968

// ---- compile-time tables (immediates in SASS) ----
constexpr int CBW[NBANDS] = {
    2,3,3,3,3,3,3,3,3,3,3,
    8,8,8,8,8,8,8,8,8,8,8,8,
    16,16,16,16,16,16,16,17
};
constexpr int KALc[NBANDS] = {
    0,4,12,20,28,36,44,52,60,68,76,
    84,100,116,132,148,164,180,196,212,228,244,260,
    276,308,340,372,404,436,468,500
};

// ---- runtime tables for the small prep kernels ----
__constant__ int c_bw[NBANDS] = {
    2,3,3,3,3,3,3,3,3,3,3,
    8,8,8,8,8,8,8,8,8,8,8,8,
    16,16,16,16,16,16,16,17
};
__constant__ int c_kal[NBANDS] = {
    0,4,12,20,28,36,44,52,60,68,76,
    84,100,116,132,148,164,180,196,212,228,244,260,
    276,308,340,372,404,436,468,500
};
__constant__ int c_f0[NBANDS] = {
    0,2,5,8,11,14,17,20,23,26,29,
    32,40,48,56,64,72,80,88,96,104,112,120,
    128,144,160,176,192,208,224,240
};
// k-slots that are zero-padding
__constant__ int c_pad[22] = {
    10,11,18,19,26,27,34,35,42,43,50,51,58,59,66,67,74,75,82,83,534,535
};

// static scratch
__device__ float  d_A2[NB * KTOT];
__device__ float  d_B2[NB * KTOT];
__device__ float  d_w2[KTOT * NO];            // interleaved-o weight rows
__device__ float  d_bp[NBANDS * NO];          // interleaved-o bias
__device__ float2 d_ps[NB * NBANDS * NCH];    // partial (sum, sumsq)

// closed-form global-k index for frequency f (component 0)
__device__ __forceinline__ int kg_of_f(int f)
{
    if (f >= 32) return 2 * f + 20;
    if (f >= 2)  return 2 * f - 2 + 2 * ((f + 1) / 3);
    return 2 * f;
}

__device__ __forceinline__ float2 u2f(unsigned long long u)
{
    float2 r;
    asm("mov.b64 {%0,%1}, %2;" : "=f"(r.x), "=f"(r.y) : "l"(u));
    return r;
}

// ---------------------------------------------------------------------------
// Stats stage 1: partial sums over a t-chunk of x[b, f0:f0+bw, :, :]
// ---------------------------------------------------------------------------
__global__ __launch_bounds__(256)
void stats1(const float* __restrict__ x)
{
    const int b    = blockIdx.x;
    const int band = blockIdx.y;
    const int ch   = blockIdx.z;
    const int bw   = c_bw[band];
    const float4* p = (const float4*)(x + (size_t)(b * NF + c_f0[band]) * (NT * 2));
    const int nv = bw * NT / 2;
    const int i0 = (int)((long long)nv * ch / NCH);
    const int i1 = (int)((long long)nv * (ch + 1) / NCH);

    float4 a1 = make_float4(0.f, 0.f, 0.f, 0.f);
    float4 a2 = a1;
    for (int i = i0 + threadIdx.x; i < i1; i += 256) {
        float4 v = p[i];
        a1.x += v.x; a1.y += v.y; a1.z += v.z; a1.w += v.w;
        a2.x = fmaf(v.x, v.x, a2.x); a2.y = fmaf(v.y, v.y, a2.y);
        a2.z = fmaf(v.z, v.z, a2.z); a2.w = fmaf(v.w, v.w, a2.w);
    }
    float s  = (a1.x + a1.y) + (a1.z + a1.w);
    float s2 = (a2.x + a2.y) + (a2.z + a2.w);
    for (int off = 16; off; off >>= 1) {
        s  += __shfl_down_sync(0xFFFFFFFFu, s,  off);
        s2 += __shfl_down_sync(0xFFFFFFFFu, s2, off);
    }
    __shared__ float sh0[8], sh1[8];
    const int w = threadIdx.x >> 5, l = threadIdx.x & 31;
    if (l == 0) { sh0[w] = s; sh1[w] = s2; }
    __syncthreads();
    if (threadIdx.x == 0) {
        float ts = 0.f, ts2 = 0.f;
        #pragma unroll
        for (int i = 0; i < 8; i++) { ts += sh0[i]; ts2 += sh1[i]; }
        d_ps[(b * NBANDS + band) * NCH + ch] = make_float2(ts, ts2);
    }
}

// ---------------------------------------------------------------------------
// Stats stage 2: deterministic fp64 combine; fold GN into per-k affine A, B.
// ---------------------------------------------------------------------------
__global__ __launch_bounds__(64)
void stats2(const float* __restrict__ gnw, const float* __restrict__ gnb)
{
    const int b    = blockIdx.x;
    const int band = blockIdx.y;
    const int bw   = c_bw[band];
    const int n    = bw * NT * 2;

    __shared__ float sh_mean, sh_inv;
    if (threadIdx.x == 0) {
        double ts = 0.0, ts2 = 0.0;
        #pragma unroll
        for (int i = 0; i < NCH; i++) {
            float2 v = d_ps[(b * NBANDS + band) * NCH + i];
            ts += (double)v.x; ts2 += (double)v.y;
        }
        double mean = ts / n;
        double var  = ts2 / n - mean * mean;
        sh_mean = (float)mean;
        sh_inv  = rsqrtf((float)var + 1e-5f);
    }
    __syncthreads();

    const int c = 2 * bw;
    if (threadIdx.x < c) {
        float gw = gnw[band * MAXC + threadIdx.x];
        float gb = gnb[band * MAXC + threadIdx.x];
        float A  = gw * sh_inv;
        int   kg = c_kal[band] + threadIdx.x;
        d_A2[b * KTOT + kg] = A;
        d_B2[b * KTOT + kg] = gb - A * sh_mean;
    }
}

// ---------------------------------------------------------------------------
// Weight/bias prep, interleaved-o: row position 4l+j holds o = l + {0,64,32,96}[j].
// ---------------------------------------------------------------------------
__global__ __launch_bounds__(256)
void prep_w(const float* __restrict__ fcw, const float* __restrict__ fcb)
{
    const int band = blockIdx.x;
    const int C    = 2 * c_bw[band];
    const int kp   = (C + 3) & ~3;
    const int kal  = c_kal[band];
    for (int idx = threadIdx.x; idx < kp * NO; idx += blockDim.x) {
        const int k = idx >> 7;
        const int p = idx & 127;
        const int l = p >> 2;
        const int j = p & 3;
        const int o = l + (j & 1) * 64 + (j >> 1) * 32;   // {0,64,32,96}
        d_w2[(kal + k) * NO + p] = (k < C) ? fcw[(band * NO + o) * MAXC + k] : 0.0f;
    }
    if (threadIdx.x < NO) {
        const int p = threadIdx.x;
        const int l = p >> 2;
        const int j = p & 3;
        const int o = l + (j & 1) * 64 + (j >> 1) * 32;
        d_bp[band * NO + p] = fcb[band * NO + o];
    }
}

// ---------------------------------------------------------------------------
// Fused kernel, TT=4, occ 2; compile-time band schedule (full unroll, ptxas
// can pipeline weight LDGs across bands). y duplicated {y,y} pairs for f32x2
// broadcast; s_out exact output order; final copy via cp.async.bulk.
// ---------------------------------------------------------------------------
#define SOUT_F   (TT * OUTW)                  // 15872 floats (63488 B)
#define SY_F     (TT * KTOT * 2)              // 4288 floats
#define SMEM_F   (SOUT_F + SY_F + 2 * KTOT)   // 21232 floats = 84928 B

#define FMA2(acc, wv, yv) \
    asm("fma.rn.f32x2 %0, %1, %2, %0;" : "+l"(acc) : "l"(wv), "l"(yv));

template <int BAND>
__device__ __forceinline__ void do_band(const unsigned long long* __restrict__ s_y2u,
                                        float* __restrict__ s_out, int lane)
{
    constexpr int kal  = KALc[BAND];
    constexpr int kcnt = (2 * CBW[BAND] + 3) & ~3;

    const ulonglong2* wp = (const ulonglong2*)(d_w2 + (size_t)kal * NO) + lane;

    unsigned long long acc[TT][2];
    {
        ulonglong2 bz = __ldg((const ulonglong2*)(d_bp + BAND * NO) + lane);
        #pragma unroll
        for (int t = 0; t < TT; t++) { acc[t][0] = bz.x; acc[t][1] = bz.y; }
    }

    const unsigned long long* yb = s_y2u + kal;   // index: t*KTOT + k

    #pragma unroll
    for (int k = 0; k < kcnt; k += 4) {
        const ulonglong2 w0 = __ldg(wp + (k + 0) * 32);
        const ulonglong2 w1 = __ldg(wp + (k + 1) * 32);
        const ulonglong2 w2 = __ldg(wp + (k + 2) * 32);
        const ulonglong2 w3 = __ldg(wp + (k + 3) * 32);
        #pragma unroll
        for (int t = 0; t < TT; t++) {
            const ulonglong2 ya = *(const ulonglong2*)(yb + t * KTOT + k);      // {y[k]x2, y[k+1]x2}
            const ulonglong2 yc = *(const ulonglong2*)(yb + t * KTOT + k + 2);  // {y[k+2]x2, y[k+3]x2}
            FMA2(acc[t][0], w0.x, ya.x) FMA2(acc[t][1], w0.y, ya.x)
            FMA2(acc[t][0], w1.x, ya.y) FMA2(acc[t][1], w1.y, ya.y)
            FMA2(acc[t][0], w2.x, yc.x) FMA2(acc[t][1], w2.y, yc.x)
            FMA2(acc[t][0], w3.x, yc.y) FMA2(acc[t][1], w3.y, yc.y)
        }
    }

    // conflict-free scalar STS: bank = (31*lane + BAND) mod 32, distinct per lane
    #pragma unroll
    for (int t = 0; t < TT; t++) {
        float* so = s_out + t * OUTW + 31 * lane + BAND;
        float2 pa = u2f(acc[t][0]);     // (o=l,    o=l+64)
        float2 pb = u2f(acc[t][1]);     // (o=l+32, o=l+96)
        so[0]    = pa.x;
        so[1984] = pa.y;                // 31*64
        so[992]  = pb.x;                // 31*32
        so[2976] = pb.y;                // 31*96
    }
}

__global__ __launch_bounds__(512, 2)
void fused_kernel(const float* __restrict__ x,
                  float* __restrict__ out)
{
    extern __shared__ float sm[];
    float* s_out = sm;                        // [t][OUTW] exact output order
    float* s_y2  = sm + SOUT_F;               // [t][KTOT] duplicated pairs
    float* s_A   = sm + SOUT_F + SY_F;
    float* s_B   = s_A + KTOT;

    const int b   = blockIdx.y;
    const int t0  = blockIdx.x * TT;
    const int tid = threadIdx.x;

    for (int i = tid; i < KTOT; i += 512) {
        s_A[i] = d_A2[b * KTOT + i];
        s_B[i] = d_B2[b * KTOT + i];
    }
    // zero only the 22 padded k-slots (w-pad is 0, but 0*uninit = NaN)
    if (tid < 22 * TT) {
        const int t    = tid / 22;
        const int slot = c_pad[tid - 22 * t];
        *(float2*)&s_y2[(t * KTOT + slot) * 2] = make_float2(0.f, 0.f);
    }
    __syncthreads();

    // y-build: y[t][kg] = A*x + B, duplicated pair written with one STS.64
    for (int idx = tid; idx < NF * 2; idx += 512) {
        const int f = idx >> 1;
        const int q = idx & 1;                // q=0 -> t0,t1 ; q=1 -> t2,t3
        const float4 v = *(const float4*)(x + ((size_t)(b * NF + f) * NT + t0) * 2 + q * 4);
        const int kg = kg_of_f(f);
        const int ta = 2 * q, tb = 2 * q + 1;
        const float A0 = s_A[kg], B0 = s_B[kg];
        const float A1 = s_A[kg + 1], B1 = s_B[kg + 1];
        float y;
        y = fmaf(A0, v.x, B0);
        *(float2*)&s_y2[(ta * KTOT + kg    ) * 2] = make_float2(y, y);
        y = fmaf(A1, v.y, B1);
        *(float2*)&s_y2[(ta * KTOT + kg + 1) * 2] = make_float2(y, y);
        y = fmaf(A0, v.z, B0);
        *(float2*)&s_y2[(tb * KTOT + kg    ) * 2] = make_float2(y, y);
        y = fmaf(A1, v.w, B1);
        *(float2*)&s_y2[(tb * KTOT + kg + 1) * 2] = make_float2(y, y);
    }
    __syncthreads();

    const int lane = tid & 31;
    const int warp = tid >> 5;
    const unsigned long long* s_y2u = (const unsigned long long*)s_y2;

    // compile-time band schedule: 16 warps, padded-C sums 32..40
    switch (warp) {
    case 0:  do_band<30>(s_y2u, s_out, lane); break;
    case 1:  do_band<23>(s_y2u, s_out, lane); break;
    case 2:  do_band<24>(s_y2u, s_out, lane); break;
    case 3:  do_band<25>(s_y2u, s_out, lane); break;
    case 4:  do_band<26>(s_y2u, s_out, lane); break;
    case 5:  do_band<27>(s_y2u, s_out, lane); break;
    case 6:  do_band<28>(s_y2u, s_out, lane); break;
    case 7:  do_band<29>(s_y2u, s_out, lane); break;
    case 8:  do_band<11>(s_y2u, s_out, lane);
             do_band<12>(s_y2u, s_out, lane); break;
    case 9:  do_band<13>(s_y2u, s_out, lane);
             do_band<14>(s_y2u, s_out, lane); break;
    case 10: do_band<15>(s_y2u, s_out, lane);
             do_band<16>(s_y2u, s_out, lane); break;
    case 11: do_band<17>(s_y2u, s_out, lane);
             do_band<18>(s_y2u, s_out, lane); break;
    case 12: do_band<19>(s_y2u, s_out, lane);
             do_band<20>(s_y2u, s_out, lane); break;
    case 13: do_band<21>(s_y2u, s_out, lane);
             do_band<22>(s_y2u, s_out, lane);
             do_band<0 >(s_y2u, s_out, lane); break;
    case 14: do_band<1 >(s_y2u, s_out, lane);
             do_band<2 >(s_y2u, s_out, lane);
             do_band<3 >(s_y2u, s_out, lane);
             do_band<4 >(s_y2u, s_out, lane);
             do_band<5 >(s_y2u, s_out, lane); break;
    default: do_band<6 >(s_y2u, s_out, lane);
             do_band<7 >(s_y2u, s_out, lane);
             do_band<8 >(s_y2u, s_out, lane);
             do_band<9 >(s_y2u, s_out, lane);
             do_band<10>(s_y2u, s_out, lane); break;
    }
    __syncthreads();

    // async bulk copy smem -> gmem (contiguous 63488 B), issued by one thread
    if (tid == 0) {
        unsigned int saddr;
        asm("{ .reg .u64 t; cvta.to.shared.u64 t, %1; cvt.u32.u64 %0, t; }"
            : "=r"(saddr) : "l"(s_out));
        float* dst = out + (size_t)(b * NT + t0) * OUTW;
        asm volatile("fence.proxy.async.shared::cta;" ::: "memory");
        asm volatile("cp.async.bulk.global.shared::cta.bulk_group [%0], [%1], %2;"
                     :: "l"(dst), "r"(saddr), "r"(SOUT_F * 4) : "memory");
        asm volatile("cp.async.bulk.commit_group;" ::: "memory");
        asm volatile("cp.async.bulk.wait_group.read 0;" ::: "memory");
    }
}

// ---------------------------------------------------------------------------
extern "C" void kernel_launch(void* const* d_in, const int* in_sizes, int n_in,
                              void* d_out, int out_size)
{
    const float* x   = (const float*)d_in[0];
    const float* gnw = (const float*)d_in[1];
    const float* gnb = (const float*)d_in[2];
    const float* fcw = (const float*)d_in[3];
    const float* fcb = (const float*)d_in[4];
    float* out = (float*)d_out;

    const int smem_bytes = SMEM_F * 4;
    cudaFuncSetAttribute(fused_kernel,
                         cudaFuncAttributeMaxDynamicSharedMemorySize, smem_bytes);

    stats1<<<dim3(NB, NBANDS, NCH), 256>>>(x);
    stats2<<<dim3(NB, NBANDS), 64>>>(gnw, gnb);
    prep_w<<<NBANDS, 256>>>(fcw, fcb);
    fused_kernel<<<dim3(NT / TT, NB), 512, smem_bytes>>>(x, out);
}

// round 9
// speedup vs baseline: 1.2132x; 1.2132x over previous
#include <cuda_runtime.h>

#define NBANDS 31
#define NB     16
#define NT     1000
#define NF     257
#define NO     128
#define MAXC   34
#define KTOT   536      // sum of roundup4(2*bw)
#define TT     4        // time tile per block
#define NCH    8        // stats chunks per (b,band)
#define OUTW   (NO * NBANDS)   // 3968
#define NTHR   384      // fused block size (12 warps, occ 2 -> 85-reg cap)

__constant__ int c_bw[NBANDS] = {
    2,3,3,3,3,3,3,3,3,3,3,
    8,8,8,8,8,8,8,8,8,8,8,8,
    16,16,16,16,16,16,16,17
};
__constant__ int c_kal[NBANDS] = {
    0,4,12,20,28,36,44,52,60,68,76,
    84,100,116,132,148,164,180,196,212,228,244,260,
    276,308,340,372,404,436,468,500
};
__constant__ int c_f0[NBANDS] = {
    0,2,5,8,11,14,17,20,23,26,29,
    32,40,48,56,64,72,80,88,96,104,112,120,
    128,144,160,176,192,208,224,240
};
// 12 band-groups (one warp each); padded-C sums: 40,48x7,40,40,40,40
__constant__ int c_gs[13] = {0,2,4,6,8,10,12,14,16,19,22,26,31};
__constant__ int c_gb[31] = {
    30,0,  23,11, 24,12, 25,13, 26,14, 27,15, 28,16, 29,17,
    18,19,1,  20,21,2,  22,3,4,5,  6,7,8,9,10
};
// k-slots that are zero-padding
__constant__ int c_pad[22] = {
    10,11,18,19,26,27,34,35,42,43,50,51,58,59,66,67,74,75,82,83,534,535
};

// static scratch
__device__ float  d_A2[NB * KTOT];
__device__ float  d_B2[NB * KTOT];
__device__ float  d_w2[KTOT * NO];            // interleaved-o weight rows
__device__ float  d_bp[NBANDS * NO];          // interleaved-o bias
__device__ float2 d_ps[NB * NBANDS * NCH];    // partial (sum, sumsq)

// closed-form global-k index for frequency f (component 0)
__device__ __forceinline__ int kg_of_f(int f)
{
    if (f >= 32) return 2 * f + 20;
    if (f >= 2)  return 2 * f - 2 + 2 * ((f + 1) / 3);
    return 2 * f;
}

__device__ __forceinline__ float2 u2f(unsigned long long u)
{
    float2 r;
    asm("mov.b64 {%0,%1}, %2;" : "=f"(r.x), "=f"(r.y) : "l"(u));
    return r;
}

// ---------------------------------------------------------------------------
// Stats stage 1: partial sums over a t-chunk of x[b, f0:f0+bw, :, :]
// ---------------------------------------------------------------------------
__global__ __launch_bounds__(256)
void stats1(const float* __restrict__ x)
{
    const int b    = blockIdx.x;
    const int band = blockIdx.y;
    const int ch   = blockIdx.z;
    const int bw   = c_bw[band];
    const float4* p = (const float4*)(x + (size_t)(b * NF + c_f0[band]) * (NT * 2));
    const int nv = bw * NT / 2;
    const int i0 = (int)((long long)nv * ch / NCH);
    const int i1 = (int)((long long)nv * (ch + 1) / NCH);

    float4 a1 = make_float4(0.f, 0.f, 0.f, 0.f);
    float4 a2 = a1;
    for (int i = i0 + threadIdx.x; i < i1; i += 256) {
        float4 v = p[i];
        a1.x += v.x; a1.y += v.y; a1.z += v.z; a1.w += v.w;
        a2.x = fmaf(v.x, v.x, a2.x); a2.y = fmaf(v.y, v.y, a2.y);
        a2.z = fmaf(v.z, v.z, a2.z); a2.w = fmaf(v.w, v.w, a2.w);
    }
    float s  = (a1.x + a1.y) + (a1.z + a1.w);
    float s2 = (a2.x + a2.y) + (a2.z + a2.w);
    for (int off = 16; off; off >>= 1) {
        s  += __shfl_down_sync(0xFFFFFFFFu, s,  off);
        s2 += __shfl_down_sync(0xFFFFFFFFu, s2, off);
    }
    __shared__ float sh0[8], sh1[8];
    const int w = threadIdx.x >> 5, l = threadIdx.x & 31;
    if (l == 0) { sh0[w] = s; sh1[w] = s2; }
    __syncthreads();
    if (threadIdx.x == 0) {
        float ts = 0.f, ts2 = 0.f;
        #pragma unroll
        for (int i = 0; i < 8; i++) { ts += sh0[i]; ts2 += sh1[i]; }
        d_ps[(b * NBANDS + band) * NCH + ch] = make_float2(ts, ts2);
    }
}

// ---------------------------------------------------------------------------
// Stage 2 merged: blockIdx.y < NB -> stats finalize (fold GN into A,B);
// blockIdx.y == NB -> weight/bias interleave prep for this band.
// ---------------------------------------------------------------------------
__global__ __launch_bounds__(256)
void stats2_prep(const float* __restrict__ gnw, const float* __restrict__ gnb,
                 const float* __restrict__ fcw, const float* __restrict__ fcb)
{
    const int band = blockIdx.x;
    const int bw   = c_bw[band];
    const int kal  = c_kal[band];

    if (blockIdx.y < NB) {
        const int b = blockIdx.y;
        const int n = bw * NT * 2;
        __shared__ float sh_mean, sh_inv;
        if (threadIdx.x == 0) {
            double ts = 0.0, ts2 = 0.0;
            #pragma unroll
            for (int i = 0; i < NCH; i++) {
                float2 v = d_ps[(b * NBANDS + band) * NCH + i];
                ts += (double)v.x; ts2 += (double)v.y;
            }
            double mean = ts / n;
            double var  = ts2 / n - mean * mean;
            sh_mean = (float)mean;
            sh_inv  = rsqrtf((float)var + 1e-5f);
        }
        __syncthreads();
        const int c = 2 * bw;
        if (threadIdx.x < c) {
            float gw = gnw[band * MAXC + threadIdx.x];
            float gb = gnb[band * MAXC + threadIdx.x];
            float A  = gw * sh_inv;
            d_A2[b * KTOT + kal + threadIdx.x] = A;
            d_B2[b * KTOT + kal + threadIdx.x] = gb - A * sh_mean;
        }
    } else {
        // weight/bias prep, interleaved-o: pos 4l+j holds o = l + {0,64,32,96}[j]
        const int C  = 2 * bw;
        const int kp = (C + 3) & ~3;
        for (int idx = threadIdx.x; idx < kp * NO; idx += 256) {
            const int k = idx >> 7;
            const int p = idx & 127;
            const int l = p >> 2;
            const int j = p & 3;
            const int o = l + (j & 1) * 64 + (j >> 1) * 32;
            d_w2[(kal + k) * NO + p] = (k < C) ? fcw[(band * NO + o) * MAXC + k] : 0.0f;
        }
        if (threadIdx.x < NO) {
            const int p = threadIdx.x;
            const int l = p >> 2;
            const int j = p & 3;
            const int o = l + (j & 1) * 64 + (j >> 1) * 32;
            d_bp[band * NO + p] = fcb[band * NO + o];
        }
    }
}

// ---------------------------------------------------------------------------
// Fused kernel, 384 threads, occ 2 (85-reg cap leaves room for the weight
// pipeline). Depth-2 software-pipelined weight LDGs; first batch prefetched
// before the y-build barrier; next band prefetched before staging stores.
// ---------------------------------------------------------------------------
#define SOUT_F   (TT * OUTW)                  // 15872 floats (63488 B)
#define SY_F     (TT * KTOT * 2)              // 4288 floats
#define SMEM_F   (SOUT_F + SY_F + 2 * KTOT)   // 21232 floats = 84928 B

#define FMA2(acc, wv, yv) \
    asm("fma.rn.f32x2 %0, %1, %2, %0;" : "+l"(acc) : "l"(wv), "l"(yv));

__global__ __launch_bounds__(NTHR, 2)
void fused_kernel(const float* __restrict__ x,
                  float* __restrict__ out)
{
    extern __shared__ float sm[];
    float* s_out = sm;                        // [t][OUTW] exact output order
    float* s_y2  = sm + SOUT_F;               // [t][KTOT] duplicated pairs
    float* s_A   = sm + SOUT_F + SY_F;
    float* s_B   = s_A + KTOT;

    const int b    = blockIdx.y;
    const int t0   = blockIdx.x * TT;
    const int tid  = threadIdx.x;
    const int lane = tid & 31;
    const int warp = tid >> 5;     // = band group (12 groups)

    // --- prefetch first band's bias + first 2 weight rows (overlaps y-build)
    int bi         = c_gs[warp];
    const int biEnd = c_gs[warp + 1];
    int band = c_gb[bi];
    int kal  = c_kal[band];
    const ulonglong2* wp = (const ulonglong2*)(d_w2 + (size_t)kal * NO) + lane;
    ulonglong2 bz = __ldg((const ulonglong2*)(d_bp + band * NO) + lane);
    ulonglong2 p0 = __ldg(wp);
    ulonglong2 p1 = __ldg(wp + 32);

    for (int i = tid; i < KTOT; i += NTHR) {
        s_A[i] = d_A2[b * KTOT + i];
        s_B[i] = d_B2[b * KTOT + i];
    }
    // zero only the 22 padded k-slots (w-pad is 0, but 0*uninit = NaN)
    if (tid < 22 * TT) {
        const int t    = tid / 22;
        const int slot = c_pad[tid - 22 * t];
        *(float2*)&s_y2[(t * KTOT + slot) * 2] = make_float2(0.f, 0.f);
    }
    __syncthreads();

    // y-build: y[t][kg] = A*x + B, duplicated pair written with one STS.64
    for (int idx = tid; idx < NF * 2; idx += NTHR) {
        const int f = idx >> 1;
        const int q = idx & 1;                // q=0 -> t0,t1 ; q=1 -> t2,t3
        const float4 v = *(const float4*)(x + ((size_t)(b * NF + f) * NT + t0) * 2 + q * 4);
        const int kg = kg_of_f(f);
        const int ta = 2 * q, tb = 2 * q + 1;
        const float A0 = s_A[kg], B0 = s_B[kg];
        const float A1 = s_A[kg + 1], B1 = s_B[kg + 1];
        float y;
        y = fmaf(A0, v.x, B0);
        *(float2*)&s_y2[(ta * KTOT + kg    ) * 2] = make_float2(y, y);
        y = fmaf(A1, v.y, B1);
        *(float2*)&s_y2[(ta * KTOT + kg + 1) * 2] = make_float2(y, y);
        y = fmaf(A0, v.z, B0);
        *(float2*)&s_y2[(tb * KTOT + kg    ) * 2] = make_float2(y, y);
        y = fmaf(A1, v.w, B1);
        *(float2*)&s_y2[(tb * KTOT + kg + 1) * 2] = make_float2(y, y);
    }
    __syncthreads();

    const unsigned long long* s_y2u = (const unsigned long long*)s_y2;

    // --- band loop, depth-2 pipelined weight stream
    for (;;) {
        const int kcnt = (2 * c_bw[band] + 3) & ~3;
        const unsigned long long* yb = s_y2u + kal;   // index: t*KTOT + k

        unsigned long long acc[TT][2];
        #pragma unroll
        for (int t = 0; t < TT; t++) { acc[t][0] = bz.x; acc[t][1] = bz.y; }

        #pragma unroll 2
        for (int k = 0; k < kcnt; k += 2) {
            const ulonglong2 w0 = p0;
            const ulonglong2 w1 = p1;
            const int kn = (k + 2 < kcnt) ? k + 2 : k;   // clamp: last iter reloads (L1 hit)
            p0 = __ldg(wp + kn * 32);
            p1 = __ldg(wp + kn * 32 + 32);
            #pragma unroll
            for (int t = 0; t < TT; t++) {
                const ulonglong2 yp = *(const ulonglong2*)(yb + t * KTOT + k);
                FMA2(acc[t][0], w0.x, yp.x) FMA2(acc[t][1], w0.y, yp.x)
                FMA2(acc[t][0], w1.x, yp.y) FMA2(acc[t][1], w1.y, yp.y)
            }
        }

        // prefetch next band before the staging stores
        const int curBand = band;
        const bool more = (++bi < biEnd);
        if (more) {
            band = c_gb[bi];
            kal  = c_kal[band];
            wp   = (const ulonglong2*)(d_w2 + (size_t)kal * NO) + lane;
            bz   = __ldg((const ulonglong2*)(d_bp + band * NO) + lane);
            p0   = __ldg(wp);
            p1   = __ldg(wp + 32);
        }

        // conflict-free scalar STS: bank = (31*lane + band) mod 32, distinct/lane
        #pragma unroll
        for (int t = 0; t < TT; t++) {
            float* so = s_out + t * OUTW + 31 * lane + curBand;
            float2 pa = u2f(acc[t][0]);     // (o=l,    o=l+64)
            float2 pb = u2f(acc[t][1]);     // (o=l+32, o=l+96)
            so[0]    = pa.x;
            so[1984] = pa.y;                // 31*64
            so[992]  = pb.x;                // 31*32
            so[2976] = pb.y;                // 31*96
        }
        if (!more) break;
    }
    __syncthreads();

    // async bulk copy smem -> gmem (contiguous 63488 B), issued by one thread
    if (tid == 0) {
        unsigned int saddr;
        asm("{ .reg .u64 t; cvta.to.shared.u64 t, %1; cvt.u32.u64 %0, t; }"
            : "=r"(saddr) : "l"(s_out));
        float* dst = out + (size_t)(b * NT + t0) * OUTW;
        asm volatile("fence.proxy.async.shared::cta;" ::: "memory");
        asm volatile("cp.async.bulk.global.shared::cta.bulk_group [%0], [%1], %2;"
                     :: "l"(dst), "r"(saddr), "r"(SOUT_F * 4) : "memory");
        asm volatile("cp.async.bulk.commit_group;" ::: "memory");
        asm volatile("cp.async.bulk.wait_group.read 0;" ::: "memory");
    }
}

// ---------------------------------------------------------------------------
extern "C" void kernel_launch(void* const* d_in, const int* in_sizes, int n_in,
                              void* d_out, int out_size)
{
    const float* x   = (const float*)d_in[0];
    const float* gnw = (const float*)d_in[1];
    const float* gnb = (const float*)d_in[2];
    const float* fcw = (const float*)d_in[3];
    const float* fcb = (const float*)d_in[4];
    float* out = (float*)d_out;

    const int smem_bytes = SMEM_F * 4;
    cudaFuncSetAttribute(fused_kernel,
                         cudaFuncAttributeMaxDynamicSharedMemorySize, smem_bytes);

    stats1<<<dim3(NB, NBANDS, NCH), 256>>>(x);
    stats2_prep<<<dim3(NBANDS, NB + 1), 256>>>(gnw, gnb, fcw, fcb);
    fused_kernel<<<dim3(NT / TT, NB), NTHR, smem_bytes>>>(x, out);
}

// round 10
// speedup vs baseline: 1.3342x; 1.0997x over previous
#include <cuda_runtime.h>

#define NBANDS 31
#define NB     16
#define NT     1000
#define NF     257
#define NO     128
#define MAXC   34
#define KTOT   536      // sum of roundup4(2*bw)
#define TT     8        // time tile per block
#define NCH    8        // stats chunks per (b,band)
#define OUTW   (NO * NBANDS)   // 3968
#define OHW    (64 * NBANDS)   // 1984 floats per (t, o-half)

__constant__ int c_bw[NBANDS] = {
    2,3,3,3,3,3,3,3,3,3,3,
    8,8,8,8,8,8,8,8,8,8,8,8,
    16,16,16,16,16,16,16,17
};
__constant__ int c_kal[NBANDS] = {
    0,4,12,20,28,36,44,52,60,68,76,
    84,100,116,132,148,164,180,196,212,228,244,260,
    276,308,340,372,404,436,468,500
};
__constant__ int c_f0[NBANDS] = {
    0,2,5,8,11,14,17,20,23,26,29,
    32,40,48,56,64,72,80,88,96,104,112,120,
    128,144,160,176,192,208,224,240
};
// 16 band-groups (one warp each); padded-C sums 32..44
__constant__ int c_gs[17] = {0,1,2,3,4,5,6,7,8,10,12,14,16,18,21,26,31};
__constant__ int c_gb[31] = {
    30,
    23,24,25,26,27,28,29,
    11,12, 13,14, 15,16, 17,18, 19,20,
    21,22,0,
    1,2,3,4,5,
    6,7,8,9,10
};
// k-slots that are zero-padding
__constant__ int c_pad[22] = {
    10,11,18,19,26,27,34,35,42,43,50,51,58,59,66,67,74,75,82,83,534,535
};

// static scratch
__device__ float  d_A2[NB * KTOT];
__device__ float  d_B2[NB * KTOT];
// per-half weights: [h][kslot][64], pos 2l+s holds o = h*64 + l + 32*s
__device__ float  d_w2h[2 * KTOT * 64];
// bias, same per-half pairing: [band][h][64]
__device__ float  d_bp[NBANDS * NO];
__device__ float2 d_ps[NB * NBANDS * NCH];    // partial (sum, sumsq)

__device__ __forceinline__ int kg_of_f(int f)
{
    if (f >= 32) return 2 * f + 20;
    if (f >= 2)  return 2 * f - 2 + 2 * ((f + 1) / 3);
    return 2 * f;
}

__device__ __forceinline__ float2 u2f(unsigned long long u)
{
    float2 r;
    asm("mov.b64 {%0,%1}, %2;" : "=f"(r.x), "=f"(r.y) : "l"(u));
    return r;
}
__device__ __forceinline__ unsigned long long dupf(float f)
{
    unsigned long long r;
    asm("mov.b64 %0, {%1, %1};" : "=l"(r) : "f"(f));
    return r;
}

// ---------------------------------------------------------------------------
// Stats stage 1: partial sums over a t-chunk of x[b, f0:f0+bw, :, :]
// ---------------------------------------------------------------------------
__global__ __launch_bounds__(256)
void stats1(const float* __restrict__ x)
{
    const int b    = blockIdx.x;
    const int band = blockIdx.y;
    const int ch   = blockIdx.z;
    const int bw   = c_bw[band];
    const float4* p = (const float4*)(x + (size_t)(b * NF + c_f0[band]) * (NT * 2));
    const int nv = bw * NT / 2;
    const int i0 = (int)((long long)nv * ch / NCH);
    const int i1 = (int)((long long)nv * (ch + 1) / NCH);

    float4 a1 = make_float4(0.f, 0.f, 0.f, 0.f);
    float4 a2 = a1;
    for (int i = i0 + threadIdx.x; i < i1; i += 256) {
        float4 v = p[i];
        a1.x += v.x; a1.y += v.y; a1.z += v.z; a1.w += v.w;
        a2.x = fmaf(v.x, v.x, a2.x); a2.y = fmaf(v.y, v.y, a2.y);
        a2.z = fmaf(v.z, v.z, a2.z); a2.w = fmaf(v.w, v.w, a2.w);
    }
    float s  = (a1.x + a1.y) + (a1.z + a1.w);
    float s2 = (a2.x + a2.y) + (a2.z + a2.w);
    for (int off = 16; off; off >>= 1) {
        s  += __shfl_down_sync(0xFFFFFFFFu, s,  off);
        s2 += __shfl_down_sync(0xFFFFFFFFu, s2, off);
    }
    __shared__ float sh0[8], sh1[8];
    const int w = threadIdx.x >> 5, l = threadIdx.x & 31;
    if (l == 0) { sh0[w] = s; sh1[w] = s2; }
    __syncthreads();
    if (threadIdx.x == 0) {
        float ts = 0.f, ts2 = 0.f;
        #pragma unroll
        for (int i = 0; i < 8; i++) { ts += sh0[i]; ts2 += sh1[i]; }
        d_ps[(b * NBANDS + band) * NCH + ch] = make_float2(ts, ts2);
    }
}

// ---------------------------------------------------------------------------
// Stage 2 merged: y < NB -> stats finalize; y == NB -> weight/bias prep.
// ---------------------------------------------------------------------------
__global__ __launch_bounds__(256)
void stats2_prep(const float* __restrict__ gnw, const float* __restrict__ gnb,
                 const float* __restrict__ fcw, const float* __restrict__ fcb)
{
    const int band = blockIdx.x;
    const int bw   = c_bw[band];
    const int kal  = c_kal[band];

    if (blockIdx.y < NB) {
        const int b = blockIdx.y;
        const int n = bw * NT * 2;
        __shared__ float sh_mean, sh_inv;
        if (threadIdx.x == 0) {
            double ts = 0.0, ts2 = 0.0;
            #pragma unroll
            for (int i = 0; i < NCH; i++) {
                float2 v = d_ps[(b * NBANDS + band) * NCH + i];
                ts += (double)v.x; ts2 += (double)v.y;
            }
            double mean = ts / n;
            double var  = ts2 / n - mean * mean;
            sh_mean = (float)mean;
            sh_inv  = rsqrtf((float)var + 1e-5f);
        }
        __syncthreads();
        const int c = 2 * bw;
        if (threadIdx.x < c) {
            float gw = gnw[band * MAXC + threadIdx.x];
            float gb = gnb[band * MAXC + threadIdx.x];
            float A  = gw * sh_inv;
            d_A2[b * KTOT + kal + threadIdx.x] = A;
            d_B2[b * KTOT + kal + threadIdx.x] = gb - A * sh_mean;
        }
    } else {
        // per-half weight prep: d_w2h[h][kal+k][2l+s] = w[o = h*64+l+32s]
        const int C  = 2 * bw;
        const int kp = (C + 3) & ~3;
        for (int idx = threadIdx.x; idx < kp * NO; idx += 256) {
            const int k = idx >> 7;
            const int p = idx & 127;
            const int h = p >> 6;
            const int r = p & 63;
            const int l = r >> 1;
            const int s = r & 1;
            const int o = h * 64 + l + 32 * s;
            d_w2h[(h * KTOT + kal + k) * 64 + 2 * l + s] =
                (k < C) ? fcw[(band * NO + o) * MAXC + k] : 0.0f;
        }
        if (threadIdx.x < NO) {
            const int p = threadIdx.x;
            const int h = p >> 6;
            const int r = p & 63;
            const int l = r >> 1;
            const int s = r & 1;
            d_bp[band * NO + p] = fcb[band * NO + h * 64 + l + 32 * s];
        }
    }
}

// ---------------------------------------------------------------------------
// Fused kernel: block = (t-tile of 8, batch, o-half). t-pair f32x2 packing:
// acc = {out[t],out[t+1]}, y natural [k][t] (LDS.64 broadcast, no dup),
// weights dup'd in-register. Depth-4 weight pipeline. Contiguous bulk stores.
// ---------------------------------------------------------------------------
#define SOUT_F   (TT * OHW)                   // 15872 floats (63488 B)
#define SY_F     (KTOT * TT)                  // 4288 floats  [k][t]
#define SMEM_F   (SOUT_F + SY_F + 2 * KTOT)   // 21232 floats = 84928 B

#define FMA2(acc, wv, yv) \
    asm("fma.rn.f32x2 %0, %1, %2, %0;" : "+l"(acc) : "l"(wv), "l"(yv));

__global__ __launch_bounds__(512, 2)
void fused_kernel(const float* __restrict__ x,
                  float* __restrict__ out)
{
    extern __shared__ float sm[];
    float* s_out = sm;                        // [t][OHW] exact output order
    float* s_y   = sm + SOUT_F;               // [k][t]
    float* s_A   = sm + SOUT_F + SY_F;
    float* s_B   = s_A + KTOT;

    const int b    = blockIdx.y;
    const int t0   = blockIdx.x * TT;
    const int h    = blockIdx.z;              // o-half
    const int tid  = threadIdx.x;
    const int lane = tid & 31;
    const int warp = tid >> 5;                // band group

    const unsigned long long* wbase =
        (const unsigned long long*)d_w2h + (size_t)h * KTOT * 32;

    // --- prefetch first band's bias + first 4 weight rows (hidden by y-build)
    int bi          = c_gs[warp];
    const int biEnd = c_gs[warp + 1];
    int band = c_gb[bi];
    int kal  = c_kal[band];
    unsigned long long bz =
        *((const unsigned long long*)(d_bp + band * NO + h * 64) + lane);
    const unsigned long long* wp = wbase + kal * 32 + lane;
    unsigned long long wq0 = wp[0];
    unsigned long long wq1 = wp[32];
    unsigned long long wq2 = wp[64];
    unsigned long long wq3 = wp[96];

    for (int i = tid; i < KTOT; i += 512) {
        s_A[i] = d_A2[b * KTOT + i];
        s_B[i] = d_B2[b * KTOT + i];
    }
    // zero the 22 padded k-slots (all 8 t's each)
    if (tid < 22 * TT) {
        const int slot = c_pad[tid >> 3];
        s_y[slot * TT + (tid & 7)] = 0.0f;
    }
    __syncthreads();

    // y-build: s_y[kg][t] = A*x + B; float4 covers (t,t+1)x(re,im) -> 2 STS.64
    for (int idx = tid; idx < NF * 4; idx += 512) {
        const int f = idx >> 2;
        const int q = idx & 3;                // t-pair q: t = t0+2q, t0+2q+1
        const float4 v = *(const float4*)(x + ((size_t)(b * NF + f) * NT + t0) * 2 + q * 4);
        const int kg = kg_of_f(f);
        const float A0 = s_A[kg], B0 = s_B[kg];
        const float A1 = s_A[kg + 1], B1 = s_B[kg + 1];
        *(float2*)&s_y[kg * TT + 2 * q] =
            make_float2(fmaf(A0, v.x, B0), fmaf(A0, v.z, B0));
        *(float2*)&s_y[(kg + 1) * TT + 2 * q] =
            make_float2(fmaf(A1, v.y, B1), fmaf(A1, v.w, B1));
    }
    __syncthreads();

    // --- band loop, depth-4 pipelined weight stream
    for (;;) {
        const int kcnt = (2 * c_bw[band] + 3) & ~3;
        const float* yb = s_y + kal * TT;

        unsigned long long acc[4][2];   // [t-pair][oA/oB]
        {
            float2 bf = u2f(bz);
            unsigned long long bA = dupf(bf.x), bB = dupf(bf.y);
            #pragma unroll
            for (int tp = 0; tp < 4; tp++) { acc[tp][0] = bA; acc[tp][1] = bB; }
        }

        #pragma unroll 4
        for (int k = 0; k < kcnt; k++) {
            const unsigned long long w = wq0;
            wq0 = wq1; wq1 = wq2; wq2 = wq3;
            const int kn = (k + 4 < kcnt) ? k + 4 : k;   // clamp (L1 hit on reload)
            wq3 = wp[kn * 32];

            float2 wf = u2f(w);
            const unsigned long long wA = dupf(wf.x);
            const unsigned long long wB = dupf(wf.y);
            #pragma unroll
            for (int tp = 0; tp < 4; tp++) {
                const unsigned long long yv =
                    *(const unsigned long long*)(yb + k * TT + 2 * tp);  // broadcast
                FMA2(acc[tp][0], wA, yv)
                FMA2(acc[tp][1], wB, yv)
            }
        }

        // prefetch next band before staging stores
        const int curBand = band;
        const bool more = (++bi < biEnd);
        if (more) {
            band = c_gb[bi];
            kal  = c_kal[band];
            wp   = wbase + kal * 32 + lane;
            bz   = *((const unsigned long long*)(d_bp + band * NO + h * 64) + lane);
            wq0 = wp[0]; wq1 = wp[32]; wq2 = wp[64]; wq3 = wp[96];
        }

        // conflict-free staging: addr = 31*lane + band (+992 for oB), both
        // strides (TT-row 1984, o-offset 992) are 0 mod 32
        #pragma unroll
        for (int tp = 0; tp < 4; tp++) {
            float* so = s_out + (2 * tp) * OHW + 31 * lane + curBand;
            float2 pa = u2f(acc[tp][0]);    // o = h*64 + lane,    t / t+1
            float2 pb = u2f(acc[tp][1]);    // o = h*64 + lane+32
            so[0]         = pa.x;
            so[OHW]       = pa.y;
            so[992]       = pb.x;
            so[OHW + 992] = pb.y;
        }
        if (!more) break;
    }
    __syncthreads();

    // per-t contiguous bulk copies: 7936 B each (o-half slab is contiguous)
    if (tid == 0) {
        unsigned int saddr;
        asm("{ .reg .u64 t; cvta.to.shared.u64 t, %1; cvt.u32.u64 %0, t; }"
            : "=r"(saddr) : "l"(s_out));
        asm volatile("fence.proxy.async.shared::cta;" ::: "memory");
        #pragma unroll
        for (int t = 0; t < TT; t++) {
            float* dst = out + (size_t)(b * NT + t0 + t) * OUTW + h * OHW;
            asm volatile("cp.async.bulk.global.shared::cta.bulk_group [%0], [%1], %2;"
                         :: "l"(dst), "r"(saddr + t * (OHW * 4)), "n"(OHW * 4)
                         : "memory");
        }
        asm volatile("cp.async.bulk.commit_group;" ::: "memory");
        asm volatile("cp.async.bulk.wait_group.read 0;" ::: "memory");
    }
}

// ---------------------------------------------------------------------------
extern "C" void kernel_launch(void* const* d_in, const int* in_sizes, int n_in,
                              void* d_out, int out_size)
{
    const float* x   = (const float*)d_in[0];
    const float* gnw = (const float*)d_in[1];
    const float* gnb = (const float*)d_in[2];
    const float* fcw = (const float*)d_in[3];
    const float* fcb = (const float*)d_in[4];
    float* out = (float*)d_out;

    const int smem_bytes = SMEM_F * 4;
    cudaFuncSetAttribute(fused_kernel,
                         cudaFuncAttributeMaxDynamicSharedMemorySize, smem_bytes);

    stats1<<<dim3(NB, NBANDS, NCH), 256>>>(x);
    stats2_prep<<<dim3(NBANDS, NB + 1), 256>>>(gnw, gnb, fcw, fcb);
    fused_kernel<<<dim3(NT / TT, NB, 2), 512, smem_bytes>>>(x, out);
}